// round 2
// baseline (speedup 1.0000x reference)
#include <cuda_runtime.h>

#define NQ 22
#define DIM (1 << NQ)
#define NL 4

// Working state (scratch; input buffers must stay pristine for graph replay)
__device__ float2 g_state[DIM];                 // 32 MB
__device__ float  g_norm_partial[1024];
__device__ float  g_inv_norm;
__device__ float2 g_U[NL][NQ][4];               // fused RZ*RY*RX per (layer,qubit)
__device__ float  g_zpart[256][22];

__device__ __forceinline__ float2 cmulf(float2 a, float2 b) {
    return make_float2(a.x * b.x - a.y * b.y, a.x * b.y + a.y * b.x);
}

// ---------------------------------------------------------------------------
// 1) Pack re/im into g_state, compute per-block sum(|a|^2)
// ---------------------------------------------------------------------------
__global__ void prep_kernel(const float* __restrict__ re, const float* __restrict__ im) {
    int tid = threadIdx.x;
    int base = blockIdx.x * 4096;
    float acc = 0.f;
#pragma unroll
    for (int k = 0; k < 16; k++) {
        int idx = base + k * 256 + tid;
        float r = re[idx], m = im[idx];
        g_state[idx] = make_float2(r, m);
        acc = fmaf(r, r, acc);
        acc = fmaf(m, m, acc);
    }
    for (int off = 16; off; off >>= 1) acc += __shfl_xor_sync(0xffffffffu, acc, off);
    __shared__ float ws[8];
    int lane = tid & 31, wp = tid >> 5;
    if (lane == 0) ws[wp] = acc;
    __syncthreads();
    if (wp == 0) {
        float v = (lane < 8) ? ws[lane] : 0.f;
        for (int off = 4; off; off >>= 1) v += __shfl_xor_sync(0xffffffffu, v, off);
        if (lane == 0) g_norm_partial[blockIdx.x] = v;
    }
}

__global__ void norm_finalize() {
    int tid = threadIdx.x;
    float v = g_norm_partial[tid];
    for (int off = 16; off; off >>= 1) v += __shfl_xor_sync(0xffffffffu, v, off);
    __shared__ float ws[32];
    int lane = tid & 31, wp = tid >> 5;
    if (lane == 0) ws[wp] = v;
    __syncthreads();
    if (wp == 0) {
        float s = ws[lane];
        for (int off = 16; off; off >>= 1) s += __shfl_xor_sync(0xffffffffu, s, off);
        if (lane == 0) g_inv_norm = rsqrtf(s);
    }
}

// ---------------------------------------------------------------------------
// 2) Build fused single-qubit unitaries  U = RZ * RY * RX
// ---------------------------------------------------------------------------
__global__ void make_gates(const float* __restrict__ params) {
    int t = threadIdx.x;
    if (t >= NL * NQ) return;
    int l = t / NQ, q = t % NQ;
    const float* p = params + (l * NQ + q) * 3;
    float tx = 0.5f * p[0], ty = 0.5f * p[1], tz = 0.5f * p[2];
    float cx = cosf(tx), sx = sinf(tx);
    float cy = cosf(ty), sy = sinf(ty);
    float cz = cosf(tz), sz = sinf(tz);
    // M = RY @ RX
    float2 m00 = make_float2( cy * cx,  sy * sx);
    float2 m01 = make_float2(-sy * cx, -cy * sx);
    float2 m10 = make_float2( sy * cx, -cy * sx);
    float2 m11 = make_float2( cy * cx, -sy * sx);
    float2 e0 = make_float2(cz, -sz);   // exp(-i tz/2)
    float2 e1 = make_float2(cz,  sz);   // exp(+i tz/2)
    g_U[l][q][0] = cmulf(e0, m00);
    g_U[l][q][1] = cmulf(e0, m01);
    g_U[l][q][2] = cmulf(e1, m10);
    g_U[l][q][3] = cmulf(e1, m11);
}

// ---------------------------------------------------------------------------
// 3a) Kernel A: tile bits {0..4} U {13..21}. Rotations qubits 0..8
//     (global bits 13..21 = local bits 5..13), then CNOTs q=0..7 as a
//     permutation of local bits 5..12 (mask 0x1FE0) at store time.
// ---------------------------------------------------------------------------
__global__ void __launch_bounds__(1024, 1) layerA_kernel(int layer, int do_scale) {
    extern __shared__ float2 sh[];
    const int tid = threadIdx.x;
    const int blk = blockIdx.x;   // global bits 5..12
    float s = do_scale ? g_inv_norm : 1.0f;
#pragma unroll
    for (int k = 0; k < 16; k++) {
        int j = k * 1024 + tid;
        int g = ((j >> 5) << 13) | (blk << 5) | (j & 31);
        float2 a = g_state[g];
        sh[j] = make_float2(a.x * s, a.y * s);
    }
    __syncthreads();
#pragma unroll
    for (int lb = 5; lb <= 13; ++lb) {
        const int q = 13 - lb;                       // qubit index
        const float2 u00 = g_U[layer][q][0];
        const float2 u01 = g_U[layer][q][1];
        const float2 u10 = g_U[layer][q][2];
        const float2 u11 = g_U[layer][q][3];
        const int lm = (1 << lb) - 1;
#pragma unroll
        for (int k = 0; k < 8; k++) {
            int p = k * 1024 + tid;
            int j0 = ((p & ~lm) << 1) | (p & lm);
            int j1 = j0 | (1 << lb);
            float2 a0 = sh[j0], a1 = sh[j1];
            float2 b0, b1;
            b0.x = u00.x*a0.x - u00.y*a0.y + u01.x*a1.x - u01.y*a1.y;
            b0.y = u00.x*a0.y + u00.y*a0.x + u01.x*a1.y + u01.y*a1.x;
            b1.x = u10.x*a0.x - u10.y*a0.y + u11.x*a1.x - u11.y*a1.y;
            b1.y = u10.x*a0.y + u10.y*a0.x + u11.x*a1.y + u11.y*a1.x;
            sh[j0] = b0;
            sh[j1] = b1;
        }
        __syncthreads();
    }
#pragma unroll
    for (int k = 0; k < 16; k++) {
        int j = k * 1024 + tid;
        int g = ((j >> 5) << 13) | (blk << 5) | (j & 31);
        g_state[g] = sh[j ^ ((j >> 1) & 0x1FE0)];   // CNOTs q=0..7
    }
}

// ---------------------------------------------------------------------------
// 3b) Kernel B: contiguous tile bits 0..13. Rotations qubits 9..21
//     (bits 0..12), then CNOTs q=8..20 as permutation (mask 0x1FFF).
// ---------------------------------------------------------------------------
__global__ void __launch_bounds__(1024, 1) layerB_kernel(int layer) {
    extern __shared__ float2 sh[];
    const int tid = threadIdx.x;
    const int base = blockIdx.x << 14;   // global bits 14..21
#pragma unroll
    for (int k = 0; k < 16; k++) {
        int j = k * 1024 + tid;
        sh[j] = g_state[base + j];
    }
    __syncthreads();
#pragma unroll
    for (int lb = 0; lb <= 12; ++lb) {
        const int q = 21 - lb;
        const float2 u00 = g_U[layer][q][0];
        const float2 u01 = g_U[layer][q][1];
        const float2 u10 = g_U[layer][q][2];
        const float2 u11 = g_U[layer][q][3];
        const int lm = (1 << lb) - 1;
#pragma unroll
        for (int k = 0; k < 8; k++) {
            int p = k * 1024 + tid;
            int j0 = ((p & ~lm) << 1) | (p & lm);
            int j1 = j0 | (1 << lb);
            float2 a0 = sh[j0], a1 = sh[j1];
            float2 b0, b1;
            b0.x = u00.x*a0.x - u00.y*a0.y + u01.x*a1.x - u01.y*a1.y;
            b0.y = u00.x*a0.y + u00.y*a0.x + u01.x*a1.y + u01.y*a1.x;
            b1.x = u10.x*a0.x - u10.y*a0.y + u11.x*a1.x - u11.y*a1.y;
            b1.y = u10.x*a0.y + u10.y*a0.x + u11.x*a1.y + u11.y*a1.x;
            sh[j0] = b0;
            sh[j1] = b1;
        }
        __syncthreads();
    }
#pragma unroll
    for (int k = 0; k < 16; k++) {
        int j = k * 1024 + tid;
        g_state[base + j] = sh[j ^ ((j >> 1) & 0x1FFF)];  // CNOTs q=8..20
    }
}

// ---------------------------------------------------------------------------
// 4) Z expectation values. Index decomposition: bits 0..9 = tid,
//    bits 10..13 = register iteration, bits 14..21 = block.
// ---------------------------------------------------------------------------
__global__ void expval_kernel() {
    __shared__ float wsum[15][33];
    int tid = threadIdx.x, blk = blockIdx.x;
    int lane = tid & 31, wp = tid >> 5;
    float T = 0.f, U0 = 0.f, U1 = 0.f, U2 = 0.f, U3 = 0.f;
    int base = blk << 14;
#pragma unroll
    for (int i = 0; i < 16; i++) {
        float2 a = g_state[base + (i << 10) + tid];
        float p = fmaf(a.x, a.x, a.y * a.y);
        T += p;
        if (i & 1) U0 += p;
        if (i & 2) U1 += p;
        if (i & 4) U2 += p;
        if (i & 8) U3 += p;
    }
    float z[15];
#pragma unroll
    for (int b = 0; b < 10; b++) z[b] = ((tid >> b) & 1) ? -T : T;
    z[10] = T - 2.f * U0;
    z[11] = T - 2.f * U1;
    z[12] = T - 2.f * U2;
    z[13] = T - 2.f * U3;
    z[14] = T;
#pragma unroll
    for (int b = 0; b < 15; b++) {
        float v = z[b];
        for (int off = 16; off; off >>= 1) v += __shfl_xor_sync(0xffffffffu, v, off);
        if (lane == 0) wsum[b][wp] = v;
    }
    __syncthreads();
    if (tid < 15) {
        float s = 0.f;
        for (int w = 0; w < 32; w++) s += wsum[tid][w];
        wsum[tid][32] = s;
    }
    __syncthreads();
    if (tid < 22) {
        float v;
        if (tid < 14) v = wsum[tid][32];
        else          v = (((blk >> (tid - 14)) & 1) ? -wsum[14][32] : wsum[14][32]);
        g_zpart[blk][tid] = v;
    }
}

__global__ void final_reduce(float* __restrict__ out) {
    int q = threadIdx.x;
    if (q >= 22) return;
    int b = 21 - q;   // qubit q <-> bit 21-q
    float s = 0.f;
    for (int i = 0; i < 256; i++) s += g_zpart[i][b];
    out[q] = s;
}

// ---------------------------------------------------------------------------
extern "C" void kernel_launch(void* const* d_in, const int* in_sizes, int n_in,
                              void* d_out, int out_size) {
    const float* params = (const float*)d_in[0];
    const float* re     = (const float*)d_in[1];
    const float* im     = (const float*)d_in[2];
    float* out = (float*)d_out;

    cudaFuncSetAttribute(layerA_kernel, cudaFuncAttributeMaxDynamicSharedMemorySize, 131072);
    cudaFuncSetAttribute(layerB_kernel, cudaFuncAttributeMaxDynamicSharedMemorySize, 131072);

    prep_kernel<<<1024, 256>>>(re, im);
    norm_finalize<<<1, 1024>>>();
    make_gates<<<1, 128>>>(params);
    for (int l = 0; l < NL; l++) {
        layerA_kernel<<<256, 1024, 131072>>>(l, l == 0 ? 1 : 0);
        layerB_kernel<<<256, 1024, 131072>>>(l);
    }
    expval_kernel<<<256, 1024>>>();
    final_reduce<<<1, 32>>>(out);
}

// round 5
// speedup vs baseline: 1.2584x; 1.2584x over previous
#include <cuda_runtime.h>

#define NQ 22
#define DIM (1 << NQ)
#define NL 4

// Working state (scratch; inputs stay pristine). AoS float2, 16B-aligned for float4 access.
__device__ __align__(16) float2 g_state[DIM];
__device__ float  g_norm_partial[1024];
__device__ float  g_inv_norm;
__device__ float2 g_Ug[NL][NQ][4];   // fused RZ*RY*RX per (layer,qubit)
__device__ float  g_zpart[256][22];

// Bank swizzle over pair-index q (8192 pairs per tile): fold bits 3..5 into 0..2.
__device__ __forceinline__ int sig(int q) { return q ^ ((q >> 3) & 7); }

struct C2 { float2 u00, u01, u10, u11; };

__device__ __forceinline__ C2 getU(int l, int q) {
    C2 c;
    c.u00 = g_Ug[l][q][0]; c.u01 = g_Ug[l][q][1];
    c.u10 = g_Ug[l][q][2]; c.u11 = g_Ug[l][q][3];
    return c;
}

// Complex 2x2 gate: x' = u00*x + u01*y ; y' = u10*x + u11*y
__device__ __forceinline__ void cgate(float2& x, float2& y, const C2& U) {
    float nxr = U.u00.x*x.x - U.u00.y*x.y + U.u01.x*y.x - U.u01.y*y.y;
    float nxi = U.u00.x*x.y + U.u00.y*x.x + U.u01.x*y.y + U.u01.y*y.x;
    float nyr = U.u10.x*x.x - U.u10.y*x.y + U.u11.x*y.x - U.u11.y*y.y;
    float nyi = U.u10.x*x.y + U.u10.y*x.x + U.u11.x*y.y + U.u11.y*y.x;
    x = make_float2(nxr, nxi);
    y = make_float2(nyr, nyi);
}

// One radix-8 pass over pair-bits pb, pb+1, pb+2 (qubits q0,q1,q2).
// If intra, also applies the gate on the in-pair bit (j bit 0) for qubit qi first.
// Each thread owns 8 float4 (16 amps); ownership partitions the 8192-pair tile.
__device__ __forceinline__ void do_pass(float4* sh4, int t, int pb,
                                        int q0, int q1, int q2, int l,
                                        bool intra, int qi) {
    const int low = t & ((1 << pb) - 1);
    const int hi  = t >> pb;
    const int qbase = (hi << (pb + 3)) | low;
    float2 a[16];
#pragma unroll
    for (int s = 0; s < 8; s++) {
        float4 v = sh4[sig(qbase | (s << pb))];
        a[2*s]   = make_float2(v.x, v.y);
        a[2*s+1] = make_float2(v.z, v.w);
    }
    if (intra) {
        C2 U = getU(l, qi);
#pragma unroll
        for (int s = 0; s < 8; s++) cgate(a[2*s], a[2*s+1], U);
    }
    {
        C2 U = getU(l, q0);
#pragma unroll
        for (int s = 0; s < 8; s++) if (!(s & 1)) {
            cgate(a[2*s],   a[2*(s|1)],   U);
            cgate(a[2*s+1], a[2*(s|1)+1], U);
        }
    }
    {
        C2 U = getU(l, q1);
#pragma unroll
        for (int s = 0; s < 8; s++) if (!(s & 2)) {
            cgate(a[2*s],   a[2*(s|2)],   U);
            cgate(a[2*s+1], a[2*(s|2)+1], U);
        }
    }
    {
        C2 U = getU(l, q2);
#pragma unroll
        for (int s = 0; s < 8; s++) if (!(s & 4)) {
            cgate(a[2*s],   a[2*(s|4)],   U);
            cgate(a[2*s+1], a[2*(s|4)+1], U);
        }
    }
#pragma unroll
    for (int s = 0; s < 8; s++) {
        sh4[sig(qbase | (s << pb))] =
            make_float4(a[2*s].x, a[2*s].y, a[2*s+1].x, a[2*s+1].y);
    }
}

// ---------------------------------------------------------------------------
// Norm reduction (reads inputs only)
// ---------------------------------------------------------------------------
__global__ void norm_part(const float* __restrict__ re, const float* __restrict__ im) {
    int tid = threadIdx.x;
    int base = blockIdx.x * 4096;
    float acc = 0.f;
#pragma unroll
    for (int k = 0; k < 16; k++) {
        int idx = base + k * 256 + tid;
        float r = re[idx], m = im[idx];
        acc = fmaf(r, r, acc);
        acc = fmaf(m, m, acc);
    }
    for (int off = 16; off; off >>= 1) acc += __shfl_xor_sync(0xffffffffu, acc, off);
    __shared__ float ws[8];
    int lane = tid & 31, wp = tid >> 5;
    if (lane == 0) ws[wp] = acc;
    __syncthreads();
    if (wp == 0) {
        float v = (lane < 8) ? ws[lane] : 0.f;
        for (int off = 4; off; off >>= 1) v += __shfl_xor_sync(0xffffffffu, v, off);
        if (lane == 0) g_norm_partial[blockIdx.x] = v;
    }
}

__global__ void norm_finalize() {
    int tid = threadIdx.x;
    float v = g_norm_partial[tid];
    for (int off = 16; off; off >>= 1) v += __shfl_xor_sync(0xffffffffu, v, off);
    __shared__ float ws[32];
    int lane = tid & 31, wp = tid >> 5;
    if (lane == 0) ws[wp] = v;
    __syncthreads();
    if (wp == 0) {
        float s = ws[lane];
        for (int off = 16; off; off >>= 1) s += __shfl_xor_sync(0xffffffffu, s, off);
        if (lane == 0) g_inv_norm = rsqrtf(s);
    }
}

// ---------------------------------------------------------------------------
// Fused single-qubit unitaries  U = RZ * RY * RX
// ---------------------------------------------------------------------------
__device__ __forceinline__ float2 cmulf(float2 a, float2 b) {
    return make_float2(a.x * b.x - a.y * b.y, a.x * b.y + a.y * b.x);
}

__global__ void make_gates(const float* __restrict__ params) {
    int t = threadIdx.x;
    if (t >= NL * NQ) return;
    int l = t / NQ, q = t % NQ;
    const float* p = params + (l * NQ + q) * 3;
    float tx = 0.5f * p[0], ty = 0.5f * p[1], tz = 0.5f * p[2];
    float cx = cosf(tx), sx = sinf(tx);
    float cy = cosf(ty), sy = sinf(ty);
    float cz = cosf(tz), sz = sinf(tz);
    float2 m00 = make_float2( cy * cx,  sy * sx);
    float2 m01 = make_float2(-sy * cx, -cy * sx);
    float2 m10 = make_float2( sy * cx, -cy * sx);
    float2 m11 = make_float2( cy * cx, -sy * sx);
    float2 e0 = make_float2(cz, -sz);
    float2 e1 = make_float2(cz,  sz);
    g_Ug[l][q][0] = cmulf(e0, m00);
    g_Ug[l][q][1] = cmulf(e0, m01);
    g_Ug[l][q][2] = cmulf(e1, m10);
    g_Ug[l][q][3] = cmulf(e1, m11);
}

// ---------------------------------------------------------------------------
// Kernel A: tile bits {0..4} U {13..21} (local bit lb>=5 <-> global bit lb+8).
// Gates qubits 0..8 (local bit lb -> qubit 13-lb; pair-bit k -> qubit 12-k).
// Passes: pair bits (4,5,6)->qubits(8,7,6); (7,8,9)->(5,4,3); (10,11,12)->(2,1,0).
// Store applies CNOTs q=0..7: pair-space gather pq = q ^ ((q>>1)&0xFF0)
// (== R2's local j ^ ((j>>1)&0x1FE0); in-pair bit untouched).
// ---------------------------------------------------------------------------
__global__ void __launch_bounds__(1024, 1)
layerA_kernel(int layer, const float* __restrict__ sre, const float* __restrict__ sim, int first) {
    extern __shared__ float4 sh4[];
    const int t = threadIdx.x;
    const int blk = blockIdx.x;

    if (first) {
        float s = g_inv_norm;
#pragma unroll
        for (int u = 0; u < 8; u++) {
            int q = u * 1024 + t;
            int j = q << 1;
            int g = ((j >> 5) << 13) | (blk << 5) | (j & 31);
            float2 r2 = *(const float2*)&sre[g];
            float2 i2 = *(const float2*)&sim[g];
            sh4[sig(q)] = make_float4(r2.x * s, i2.x * s, r2.y * s, i2.y * s);
        }
    } else {
#pragma unroll
        for (int u = 0; u < 8; u++) {
            int q = u * 1024 + t;
            int j = q << 1;
            int g = ((j >> 5) << 13) | (blk << 5) | (j & 31);
            sh4[sig(q)] = *(const float4*)&g_state[g];
        }
    }
    __syncthreads();

    do_pass(sh4, t, 4,  8, 7, 6, layer, false, 0); __syncthreads();
    do_pass(sh4, t, 7,  5, 4, 3, layer, false, 0); __syncthreads();
    do_pass(sh4, t, 10, 2, 1, 0, layer, false, 0); __syncthreads();

#pragma unroll
    for (int u = 0; u < 8; u++) {
        int q = u * 1024 + t;
        int j = q << 1;
        int g = ((j >> 5) << 13) | (blk << 5) | (j & 31);
        int pq = q ^ ((q >> 1) & 0xFF0);
        *(float4*)&g_state[g] = sh4[sig(pq)];
    }
}

// ---------------------------------------------------------------------------
// Kernel B: contiguous tile bits 0..13. Gates qubits 9..21 (j bit b -> 21-b;
// pair-bit k -> qubit 20-k; in-pair bit -> qubit 21).
// Passes: in-pair + pair bits (0,1,2)->(21;20,19,18); (3,4,5)->(17,16,15);
// (6,7,8)->(14,13,12); (9,10,11)->(11,10,9).
// Store applies CNOTs q=8..20: pq = q ^ ((q>>1)&0xFFF) (== R2's 0x1FFF),
// halves swapped iff q odd (out bit0 = j0 ^ j1).
// ---------------------------------------------------------------------------
__global__ void __launch_bounds__(1024, 1)
layerB_kernel(int layer) {
    extern __shared__ float4 sh4[];
    const int t = threadIdx.x;
    const int base = blockIdx.x << 14;

#pragma unroll
    for (int u = 0; u < 8; u++) {
        int q = u * 1024 + t;
        sh4[sig(q)] = *(const float4*)&g_state[base + (q << 1)];
    }
    __syncthreads();

    do_pass(sh4, t, 0, 20, 19, 18, layer, true, 21); __syncthreads();
    do_pass(sh4, t, 3, 17, 16, 15, layer, false, 0); __syncthreads();
    do_pass(sh4, t, 6, 14, 13, 12, layer, false, 0); __syncthreads();
    do_pass(sh4, t, 9, 11, 10,  9, layer, false, 0); __syncthreads();

    const bool swp = (t & 1) != 0;
#pragma unroll
    for (int u = 0; u < 8; u++) {
        int q = u * 1024 + t;
        int pq = q ^ ((q >> 1) & 0xFFF);
        float4 v = sh4[sig(pq)];
        if (swp) v = make_float4(v.z, v.w, v.x, v.y);
        *(float4*)&g_state[base + (q << 1)] = v;
    }
}

// ---------------------------------------------------------------------------
// Z expectation values. bits 0..9 = tid, 10..13 = reg iter, 14..21 = block.
// g_state holds the true final state (permutations applied at layerB store).
// ---------------------------------------------------------------------------
__global__ void expval_kernel() {
    __shared__ float wsum[15][33];
    int tid = threadIdx.x, blk = blockIdx.x;
    int lane = tid & 31, wp = tid >> 5;
    float T = 0.f, U0 = 0.f, U1 = 0.f, U2 = 0.f, U3 = 0.f;
    int base = blk << 14;
#pragma unroll
    for (int i = 0; i < 16; i++) {
        float2 a = g_state[base + (i << 10) + tid];
        float p = fmaf(a.x, a.x, a.y * a.y);
        T += p;
        if (i & 1) U0 += p;
        if (i & 2) U1 += p;
        if (i & 4) U2 += p;
        if (i & 8) U3 += p;
    }
    float z[15];
#pragma unroll
    for (int b = 0; b < 10; b++) z[b] = ((tid >> b) & 1) ? -T : T;
    z[10] = T - 2.f * U0;
    z[11] = T - 2.f * U1;
    z[12] = T - 2.f * U2;
    z[13] = T - 2.f * U3;
    z[14] = T;
#pragma unroll
    for (int b = 0; b < 15; b++) {
        float v = z[b];
        for (int off = 16; off; off >>= 1) v += __shfl_xor_sync(0xffffffffu, v, off);
        if (lane == 0) wsum[b][wp] = v;
    }
    __syncthreads();
    if (tid < 15) {
        float s = 0.f;
        for (int w = 0; w < 32; w++) s += wsum[tid][w];
        wsum[tid][32] = s;
    }
    __syncthreads();
    if (tid < 22) {
        float v;
        if (tid < 14) v = wsum[tid][32];
        else          v = (((blk >> (tid - 14)) & 1) ? -wsum[14][32] : wsum[14][32]);
        g_zpart[blk][tid] = v;
    }
}

__global__ void final_reduce(float* __restrict__ out) {
    int q = threadIdx.x;
    if (q >= 22) return;
    int b = 21 - q;   // qubit q <-> bit 21-q
    float s = 0.f;
    for (int i = 0; i < 256; i++) s += g_zpart[i][b];
    out[q] = s;
}

// ---------------------------------------------------------------------------
extern "C" void kernel_launch(void* const* d_in, const int* in_sizes, int n_in,
                              void* d_out, int out_size) {
    const float* params = (const float*)d_in[0];
    const float* re     = (const float*)d_in[1];
    const float* im     = (const float*)d_in[2];
    float* out = (float*)d_out;

    cudaFuncSetAttribute(layerA_kernel, cudaFuncAttributeMaxDynamicSharedMemorySize, 131072);
    cudaFuncSetAttribute(layerB_kernel, cudaFuncAttributeMaxDynamicSharedMemorySize, 131072);

    norm_part<<<1024, 256>>>(re, im);
    norm_finalize<<<1, 1024>>>();
    make_gates<<<1, 128>>>(params);
    for (int l = 0; l < NL; l++) {
        layerA_kernel<<<256, 1024, 131072>>>(l, re, im, l == 0 ? 1 : 0);
        layerB_kernel<<<256, 1024, 131072>>>(l);
    }
    expval_kernel<<<256, 1024>>>();
    final_reduce<<<1, 32>>>(out);
}